// round 16
// baseline (speedup 1.0000x reference)
#include <cuda_runtime.h>
#include <cuda_fp16.h>
#include <cuda_bf16.h>
#include <cstdint>

// ---------------------------------------------------------------------------
// KimiDeltaAttention — mma.sync fp16 GEMMs (A hi/lo split, W fp16; 2 MMAs per
// product, fp32 accum; 3-stage pipeline, fused l2norm epilogue, merged qkv,
// MT-templated tiles w/ merged 64-row skinny GEMMs) + fp32 scan.
// B=4, T=2048, HID=2048, H=16, DK=DV=128
// compute_103 PTX only (no 'a' features): tensor path = mma.sync m16n8k16 f16.
// R16 fix: W tile is ALWAYS 128 rows -> separate TILE_A / TILE_W sizing
// (R15 sized both by MT, overflowing smem for MT=64 -> illegal access).
// ---------------------------------------------------------------------------

#define Bc 4
#define Tc 2048
#define HIDc 2048
#define Hc 16
#define DKc 128
#define DVc 128
#define Mc (Bc * Tc)            // 8192 rows

typedef unsigned long long ull;
typedef unsigned int u32;

// ------------------------- fp32 scratch (device globals) -------------------
__device__ float g_q   [(size_t)Mc * HIDc];
__device__ float g_k   [(size_t)Mc * HIDc];
__device__ float g_v   [(size_t)Mc * HIDc];
__device__ float g_eg  [(size_t)Mc * HIDc];   // exp(gate)
__device__ float g_sigf[(size_t)Mc * HIDc];   // sigmoid(factor)
__device__ float g_o   [(size_t)Mc * HIDc];
__device__ float g_beta[(size_t)Mc * Hc];

#define ID_Q    0
#define ID_K    1
#define ID_V    2
#define ID_EG   3
#define ID_SIGF 4
#define ID_O    5
#define ID_BETA 6

__device__ __forceinline__ float* scratch_resolve(int id) {
    switch (id) {
        case ID_Q:    return g_q;
        case ID_K:    return g_k;
        case ID_V:    return g_v;
        case ID_EG:   return g_eg;
        case ID_SIGF: return g_sigf;
        case ID_O:    return g_o;
        default:      return g_beta;
    }
}

// ------------------------- fp16 split pool ---------------------------------
constexpr size_t BS_W       = (size_t)HIDc * HIDc;
constexpr size_t BS_W0      = (size_t)128 * HIDc;
constexpr size_t OFF_HB_HI  = 0;
constexpr size_t OFF_HB_LO  = OFF_HB_HI  + (size_t)Mc * HIDc;
constexpr size_t OFF_WQ_HI  = OFF_HB_LO  + (size_t)Mc * HIDc;   // WQ,WK,WV consecutive
constexpr size_t OFF_WK_HI  = OFF_WQ_HI  + BS_W;
constexpr size_t OFF_WV_HI  = OFF_WK_HI  + BS_W;
constexpr size_t OFF_WO_HI  = OFF_WV_HI  + BS_W;
constexpr size_t OFF_FW0_HI = OFF_WO_HI  + BS_W;                // FW0,GW0 consecutive
constexpr size_t OFF_GW0_HI = OFF_FW0_HI + BS_W0;
constexpr size_t OFF_FW1_HI = OFF_GW0_HI + BS_W0;
constexpr size_t OFF_GW1_HI = OFF_FW1_HI + (size_t)HIDc * 128;
constexpr size_t OFF_TMP_HI = OFF_GW1_HI + (size_t)HIDc * 128;  // TMP,TMP2 blocks consecutive
constexpr size_t OFF_TMP_LO = OFF_TMP_HI + (size_t)Mc * 128;
constexpr size_t OFF_TMP2_HI= OFF_TMP_LO + (size_t)Mc * 128;
constexpr size_t OFF_TMP2_LO= OFF_TMP2_HI+ (size_t)Mc * 128;
constexpr size_t OFF_OG_HI  = OFF_TMP2_LO+ (size_t)Mc * 128;
constexpr size_t OFF_OG_LO  = OFF_OG_HI  + (size_t)Mc * HIDc;
constexpr size_t HF_TOTAL   = OFF_OG_LO  + (size_t)Mc * HIDc;

__device__ __half g_hfpool[HF_TOTAL];

// ------------------------------ f32x2 helpers ------------------------------
__device__ __forceinline__ ull f2pack(float a, float b) {
    ull r; asm("mov.b64 %0, {%1, %2};" : "=l"(r) : "f"(a), "f"(b)); return r;
}
__device__ __forceinline__ float2 f2unpack(ull x) {
    float2 r; asm("mov.b64 {%0, %1}, %2;" : "=f"(r.x), "=f"(r.y) : "l"(x)); return r;
}
__device__ __forceinline__ ull ffma2(ull a, ull b, ull c) {
    ull d; asm("fma.rn.f32x2 %0, %1, %2, %3;" : "=l"(d) : "l"(a), "l"(b), "l"(c)); return d;
}
__device__ __forceinline__ ull fmul2(ull a, ull b) {
    ull d; asm("mul.rn.f32x2 %0, %1, %2;" : "=l"(d) : "l"(a), "l"(b)); return d;
}
__device__ __forceinline__ ull fadd2(ull a, ull b) {
    ull d; asm("add.rn.f32x2 %0, %1, %2;" : "=l"(d) : "l"(a), "l"(b)); return d;
}

// ------------------------------ async copy ---------------------------------
__device__ __forceinline__ void cp16(void* s, const void* g) {
    u32 sa = (u32)__cvta_generic_to_shared(s);
    asm volatile("cp.async.ca.shared.global [%0], [%1], 16;" :: "r"(sa), "l"(g));
}
__device__ __forceinline__ void cp16u(u32 s, const void* g) {
    asm volatile("cp.async.cg.shared.global [%0], [%1], 16;" :: "r"(s), "l"(g));
}
__device__ __forceinline__ void cp4(void* s, const void* g) {
    u32 sa = (u32)__cvta_generic_to_shared(s);
    asm volatile("cp.async.ca.shared.global [%0], [%1], 4;" :: "r"(sa), "l"(g));
}
__device__ __forceinline__ void cp_commit() { asm volatile("cp.async.commit_group;"); }

__device__ __forceinline__ u32 smem_u32(const void* p) {
    return (u32)__cvta_generic_to_shared(p);
}

// ------------------------------ mma helpers --------------------------------
__device__ __forceinline__ void mma16816(float* c, const u32* a, const u32* b) {
    asm volatile(
        "mma.sync.aligned.m16n8k16.row.col.f32.f16.f16.f32 "
        "{%0,%1,%2,%3}, {%4,%5,%6,%7}, {%8,%9}, {%0,%1,%2,%3};"
        : "+f"(c[0]), "+f"(c[1]), "+f"(c[2]), "+f"(c[3])
        : "r"(a[0]), "r"(a[1]), "r"(a[2]), "r"(a[3]), "r"(b[0]), "r"(b[1]));
}
__device__ __forceinline__ void ldsm4(u32* r, u32 addr) {
    asm volatile("ldmatrix.sync.aligned.m8n8.x4.shared.b16 {%0,%1,%2,%3}, [%4];"
        : "=r"(r[0]), "=r"(r[1]), "=r"(r[2]), "=r"(r[3]) : "r"(addr));
}

// ------------------------------ merged split -------------------------------
constexpr u32 NB_HB  = (u32)((size_t)Mc * HIDc / 1024);    // 16384
constexpr u32 NB_W   = (u32)(BS_W / 1024);                  //  4096
constexpr u32 NB_W0  = (u32)(BS_W0 / 1024);                 //   256
constexpr u32 CUM0 = NB_HB;                  // h
constexpr u32 CUM1 = CUM0 + NB_W;            // q_w
constexpr u32 CUM2 = CUM1 + NB_W;            // k_w
constexpr u32 CUM3 = CUM2 + NB_W;            // v_w
constexpr u32 CUM4 = CUM3 + NB_W;            // o_w
constexpr u32 CUM5 = CUM4 + NB_W0;           // f_w0
constexpr u32 CUM6 = CUM5 + NB_W0;           // g_w0
constexpr u32 CUM7 = CUM6 + NB_W0;           // f_w1
constexpr u32 CUM8 = CUM7 + NB_W0;           // g_w1  (total 33792)

__global__ __launch_bounds__(256) void split_all(
    const float* __restrict__ h,   const float* __restrict__ q_w,
    const float* __restrict__ k_w, const float* __restrict__ v_w,
    const float* __restrict__ o_w, const float* __restrict__ f_w0,
    const float* __restrict__ g_w0,const float* __restrict__ f_w1,
    const float* __restrict__ g_w1)
{
    const u32 b = blockIdx.x;
    const float* src; size_t off_hi; size_t off_lo = 0; u32 b0;
    if      (b < CUM0) { src = h;    off_hi = OFF_HB_HI;  off_lo = OFF_HB_LO; b0 = 0; }
    else if (b < CUM1) { src = q_w;  off_hi = OFF_WQ_HI;  b0 = CUM0; }
    else if (b < CUM2) { src = k_w;  off_hi = OFF_WK_HI;  b0 = CUM1; }
    else if (b < CUM3) { src = v_w;  off_hi = OFF_WV_HI;  b0 = CUM2; }
    else if (b < CUM4) { src = o_w;  off_hi = OFF_WO_HI;  b0 = CUM3; }
    else if (b < CUM5) { src = f_w0; off_hi = OFF_FW0_HI; b0 = CUM4; }
    else if (b < CUM6) { src = g_w0; off_hi = OFF_GW0_HI; b0 = CUM5; }
    else if (b < CUM7) { src = f_w1; off_hi = OFF_FW1_HI; b0 = CUM6; }
    else               { src = g_w1; off_hi = OFF_GW1_HI; b0 = CUM7; }

    size_t i = ((size_t)(b - b0) * 256 + threadIdx.x) * 4;
    float4 x = *(const float4*)(src + i);
    __half h0 = __float2half_rn(x.x), h1 = __float2half_rn(x.y);
    __half h2 = __float2half_rn(x.z), h3 = __float2half_rn(x.w);
    uint2 ph;
    ph.x = (u32)__half_as_ushort(h0) | ((u32)__half_as_ushort(h1) << 16);
    ph.y = (u32)__half_as_ushort(h2) | ((u32)__half_as_ushort(h3) << 16);
    *(uint2*)(g_hfpool + off_hi + i) = ph;
    if (off_lo) {
        __half l0 = __float2half_rn(x.x - __half2float(h0));
        __half l1 = __float2half_rn(x.y - __half2float(h1));
        __half l2 = __float2half_rn(x.z - __half2float(h2));
        __half l3 = __float2half_rn(x.w - __half2float(h3));
        uint2 pl;
        pl.x = (u32)__half_as_ushort(l0) | ((u32)__half_as_ushort(l1) << 16);
        pl.y = (u32)__half_as_ushort(l2) | ((u32)__half_as_ushort(l3) << 16);
        *(uint2*)(g_hfpool + off_lo + i) = pl;
    }
}

// ------------------------- mma.sync fp16 GEMM ------------------------------
// C[M,N] = act( A[M,K] @ W[N,K]^T ), A split hi/lo, W fp16-hi:
//   D += Ahi*Whi + Alo*Whi   (fp32 accumulators)
// CTA tile MTx128 (MT=128 or 64), 256 thr (8 warps 2x4; warp tile (MT/2)x32),
// BK=32, 3-stage cp.async pipeline (one barrier/chunk), XOR-swizzled smem.
// Stage layout: [Ahi: MT rows][Alo: MT rows][Whi: 128 rows]  (TILE_A,TILE_A,TILE_W)
// ACT: 0 none | 2 kda-gate->exp | 3 sigmoid(x+aux1[n])
//      | 5 merged qkv: z=0 silu+l2norm*0.0884, z=1 silu+l2norm, z=2 silu
// Output: Cid>=0 scratch fp32 (ACT5: id Cid+z) | -1 Cext fp32 | -2 fp16 hi/lo.
// z strides: weight block = w_hi + z*w_zstride; fp16 out = (o_hi/o_lo)+z*o_zstride.
constexpr int BKg = 32;

template <int MT> struct GemmSmem {
    static constexpr int TILE_A  = MT  * BKg * 2;
    static constexpr int TILE_W  = 128 * BKg * 2;
    static constexpr int STAGE_B = 2 * TILE_A + TILE_W;
    static constexpr int TOTAL   = 3 * STAGE_B;
};

template <int ACT, int MT>
__global__ __launch_bounds__(256) void mma_gemm(
    size_t a_hi, size_t a_lo, size_t w_hi,
    float* __restrict__ Cext, int Cid, int Ntot, int Ktot,
    const float* __restrict__ aux1, const float* __restrict__ aux2,
    size_t o_hi, size_t o_lo, size_t w_zstride, size_t o_zstride)
{
    constexpr int MI = MT / 32;                    // mi-loop count
    constexpr int TILE_A  = GemmSmem<MT>::TILE_A;
    constexpr int TILE_W  = GemmSmem<MT>::TILE_W;
    constexpr int STAGE_B = GemmSmem<MT>::STAGE_B;
    constexpr int LDI = (MT * 4) / 256;            // loader iters per A tile

    extern __shared__ char dsm[];
    const u32 sb = smem_u32(dsm);
    const int tid = threadIdx.x, lane = tid & 31, wid = tid >> 5;
    const int warp_m = wid & 1, warp_n = wid >> 1;    // 2 x 4 warp grid
    const int bm = blockIdx.y, bn = blockIdx.x, bz = blockIdx.z;

    const __half* srcs[3] = {
        g_hfpool + a_hi + (size_t)bm * MT * Ktot,
        g_hfpool + a_lo + (size_t)bm * MT * Ktot,
        g_hfpool + w_hi + (size_t)bz * w_zstride + (size_t)bn * 128 * Ktot };

    float acc[MI][4][4];
#pragma unroll
    for (int i = 0; i < MI; i++)
#pragma unroll
        for (int j = 0; j < 4; j++)
#pragma unroll
            for (int e = 0; e < 4; e++) acc[i][j][e] = 0.f;

    const int NC = Ktot / BKg;
    const int jq = lane >> 3, rq = lane & 7;
    const int jlow = jq & 1, jhi = jq >> 1;

    // stage loader. A tiles have MT rows; W tile always 128 rows.
    auto load_stage = [&](int stage, int c) {
        u32 base = sb + (u32)stage * STAGE_B;
#pragma unroll
        for (int t = 0; t < 2; t++) {
            const __half* src = srcs[t] + (size_t)c * BKg;
            u32 tb = base + (u32)t * TILE_A;
#pragma unroll
            for (int i = 0; i < LDI; i++) {
                int idx = tid + i * 256;
                u32 row = (u32)(idx >> 2), g = (u32)(idx & 3);
                u32 so = tb + row * 64u + ((g ^ (row & 3u)) * 16u);
                cp16u(so, (const char*)(src + (size_t)row * Ktot) + g * 16);
            }
        }
        {   // W tile: 128 rows always
            const __half* src = srcs[2] + (size_t)c * BKg;
            u32 tb = base + 2u * TILE_A;
#pragma unroll
            for (int i = 0; i < 2; i++) {
                int idx = tid + i * 256;
                u32 row = (u32)(idx >> 2), g = (u32)(idx & 3);
                u32 so = tb + row * 64u + ((g ^ (row & 3u)) * 16u);
                cp16u(so, (const char*)(src + (size_t)row * Ktot) + g * 16);
            }
        }
    };

    load_stage(0, 0); cp_commit();
    load_stage(1, 1); cp_commit();

    int s_cur = 0, s_pre = 2;
    for (int c = 0; c < NC; c++) {
        if (c == NC - 1) {
            asm volatile("cp.async.wait_group 0;" ::: "memory");
        } else {
            asm volatile("cp.async.wait_group 1;" ::: "memory");
        }
        __syncthreads();
        if (c + 2 < NC) {
            load_stage(s_pre, c + 2); cp_commit();
        }

        const u32 base = sb + (u32)s_cur * STAGE_B;
        const u32 ah = base, al = base + TILE_A;
        const u32 wh = base + 2 * TILE_A;

#pragma unroll
        for (int ks = 0; ks < 2; ks++) {
            const u32 g = (u32)(ks * 2 + jhi);
            u32 a_hi_f[MI][4], a_lo_f[MI][4];
#pragma unroll
            for (int mi = 0; mi < MI; mi++) {
                u32 row = (u32)(warp_m * (MT / 2) + mi * 16 + jlow * 8 + rq);
                u32 off = row * 64u + ((g ^ (row & 3u)) * 16u);
                ldsm4(a_hi_f[mi], ah + off);
                ldsm4(a_lo_f[mi], al + off);
            }
            u32 b_hi_f[4][2];
#pragma unroll
            for (int pi = 0; pi < 2; pi++) {
                u32 row = (u32)(warp_n * 32 + pi * 16 + jlow * 8 + rq);
                u32 off = row * 64u + ((g ^ (row & 3u)) * 16u);
                u32 t0[4];
                ldsm4(t0, wh + off);
                b_hi_f[2*pi][0] = t0[0]; b_hi_f[2*pi][1] = t0[2];
                b_hi_f[2*pi+1][0] = t0[1]; b_hi_f[2*pi+1][1] = t0[3];
            }
#pragma unroll
            for (int mi = 0; mi < MI; mi++)
#pragma unroll
                for (int ni = 0; ni < 4; ni++) {
                    mma16816(acc[mi][ni], a_hi_f[mi], b_hi_f[ni]);
                    mma16816(acc[mi][ni], a_lo_f[mi], b_hi_f[ni]);
                }
        }
        s_cur = (s_cur == 2) ? 0 : s_cur + 1;
        s_pre = (s_pre == 2) ? 0 : s_pre + 1;
    }

    // ---------------- epilogue ----------------
    const int qrow = lane >> 2, qcol = (lane & 3) * 2;
    const int n_warp0 = bn * 128 + warp_n * 32;

    if (ACT == 5) {
#pragma unroll
        for (int mi = 0; mi < MI; mi++)
#pragma unroll
            for (int ni = 0; ni < 4; ni++)
#pragma unroll
                for (int e = 0; e < 4; e++) {
                    float x = acc[mi][ni][e];
                    acc[mi][ni][e] = x / (1.0f + expf(-x));
                }
        float* C = scratch_resolve(Cid + bz);
        if (bz < 2) {
            const float sscale = (bz == 0) ? 0.08838834764831845f : 1.0f;
            __syncthreads();
            float* red = (float*)dsm;             // [MT rows][4 warp_n]
#pragma unroll
            for (int mi = 0; mi < MI; mi++)
#pragma unroll
                for (int half = 0; half < 2; half++) {
                    float ss = 0.f;
#pragma unroll
                    for (int ni = 0; ni < 4; ni++) {
                        float x0 = acc[mi][ni][half * 2];
                        float x1 = acc[mi][ni][half * 2 + 1];
                        ss += x0 * x0 + x1 * x1;
                    }
                    ss += __shfl_xor_sync(0xffffffffu, ss, 1);
                    ss += __shfl_xor_sync(0xffffffffu, ss, 2);
                    if ((lane & 3) == 0) {
                        int rowl = warp_m * (MT / 2) + mi * 16 + half * 8 + qrow;
                        red[rowl * 4 + warp_n] = ss;
                    }
                }
            __syncthreads();
#pragma unroll
            for (int mi = 0; mi < MI; mi++)
#pragma unroll
                for (int half = 0; half < 2; half++) {
                    int rowl = warp_m * (MT / 2) + mi * 16 + half * 8 + qrow;
                    float tot = red[rowl * 4] + red[rowl * 4 + 1]
                              + red[rowl * 4 + 2] + red[rowl * 4 + 3];
                    float r = rsqrtf(tot + 1e-6f) * sscale;
                    const int m = bm * MT + rowl;
                    float* crow = C + (size_t)m * Ntot + n_warp0;
#pragma unroll
                    for (int ni = 0; ni < 4; ni++) {
                        float2 o2;
                        o2.x = acc[mi][ni][half * 2]     * r;
                        o2.y = acc[mi][ni][half * 2 + 1] * r;
                        *(float2*)(crow + ni * 8 + qcol) = o2;
                    }
                }
        } else {
#pragma unroll
            for (int mi = 0; mi < MI; mi++)
#pragma unroll
                for (int half = 0; half < 2; half++) {
                    const int m = bm * MT + warp_m * (MT / 2) + mi * 16 + half * 8 + qrow;
                    float* crow = C + (size_t)m * Ntot + n_warp0;
#pragma unroll
                    for (int ni = 0; ni < 4; ni++) {
                        float2 o2;
                        o2.x = acc[mi][ni][half * 2];
                        o2.y = acc[mi][ni][half * 2 + 1];
                        *(float2*)(crow + ni * 8 + qcol) = o2;
                    }
                }
        }
        return;
    }

    float* C = (Cid >= 0) ? scratch_resolve(Cid) : Cext;
    const size_t oh = o_hi + (size_t)bz * o_zstride;
    const size_t ol = o_lo + (size_t)bz * o_zstride;
#pragma unroll
    for (int mi = 0; mi < MI; mi++) {
#pragma unroll
        for (int half = 0; half < 2; half++) {
            const int m = bm * MT + warp_m * (MT / 2) + mi * 16 + half * 8 + qrow;
#pragma unroll
            for (int ni = 0; ni < 4; ni++) {
                float x0 = acc[mi][ni][half * 2];
                float x1 = acc[mi][ni][half * 2 + 1];
                const int n = n_warp0 + ni * 8 + qcol;
                if (ACT == 2) {
                    float a0 = expf(aux1[n >> 7]);
                    float a1 = expf(aux1[(n + 1) >> 7]);
                    float s0 = x0 + aux2[n], s1 = x1 + aux2[n + 1];
                    s0 = (s0 > 20.0f) ? s0 : log1pf(expf(s0));
                    s1 = (s1 > 20.0f) ? s1 : log1pf(expf(s1));
                    x0 = expf(-a0 * s0); x1 = expf(-a1 * s1);
                } else if (ACT == 3) {
                    x0 = 1.0f / (1.0f + expf(-(x0 + aux1[n])));
                    x1 = 1.0f / (1.0f + expf(-(x1 + aux1[n + 1])));
                }
                if (Cid == -2) {
                    __half h0 = __float2half_rn(x0), h1 = __float2half_rn(x1);
                    __half l0 = __float2half_rn(x0 - __half2float(h0));
                    __half l1 = __float2half_rn(x1 - __half2float(h1));
                    size_t base = (size_t)m * Ntot + n;
                    *(u32*)(g_hfpool + oh + base) =
                        (u32)__half_as_ushort(h0) | ((u32)__half_as_ushort(h1) << 16);
                    *(u32*)(g_hfpool + ol + base) =
                        (u32)__half_as_ushort(l0) | ((u32)__half_as_ushort(l1) << 16);
                } else {
                    float2 o2; o2.x = x0; o2.y = x1;
                    *(float2*)(C + (size_t)m * Ntot + n) = o2;
                }
            }
        }
    }
}

// --------------------------- beta = sigmoid(h @ b_w^T) ---------------------
__global__ __launch_bounds__(512) void beta_kernel(
    const float* __restrict__ H, const float* __restrict__ BW)
{
    float* BETA = scratch_resolve(ID_BETA);
    const int m = blockIdx.x;
    const int w = threadIdx.x >> 5, lane = threadIdx.x & 31;
    const float4* hr = (const float4*)(H + (size_t)m * HIDc);
    const float4* br = (const float4*)(BW + (size_t)w * HIDc);
    float s = 0.f;
#pragma unroll 4
    for (int i = lane; i < HIDc / 4; i += 32) {
        float4 a = hr[i], b = br[i];
        s += a.x * b.x + a.y * b.y + a.z * b.z + a.w * b.w;
    }
#pragma unroll
    for (int off = 16; off > 0; off >>= 1)
        s += __shfl_xor_sync(0xffffffffu, s, off);
    if (lane == 0) BETA[(size_t)m * Hc + w] = 1.0f / (1.0f + expf(-s));
}

// ---------- gated RMS norm: og = rms(o)*w*sigf, emitted as fp16 hi/lo ------
__global__ __launch_bounds__(128) void gate_kernel(const float* __restrict__ NW)
{
    const float* O    = scratch_resolve(ID_O);
    const float* SIGF = scratch_resolve(ID_SIGF);
    const int h = blockIdx.x, m = blockIdx.y;
    const int v = threadIdx.x;
    const size_t off = (size_t)m * HIDc + (size_t)h * DVc + v;
    float x = O[off];
    float s = x * x;
#pragma unroll
    for (int o = 16; o > 0; o >>= 1) s += __shfl_xor_sync(0xffffffffu, s, o);
    __shared__ float red[4];
    if ((v & 31) == 0) red[v >> 5] = s;
    __syncthreads();
    float tot = red[0] + red[1] + red[2] + red[3];
    float r = rsqrtf(tot * (1.0f / DVc) + 1e-5f);
    float y = x * r * NW[v] * SIGF[off];
    __half hi = __float2half_rn(y);
    __half lo = __float2half_rn(y - __half2float(hi));
    g_hfpool[OFF_OG_HI + off] = hi;
    g_hfpool[OFF_OG_LO + off] = lo;
}

// ------------------------------ recurrent scan -----------------------------
#define SROW 144
#define SKW(i) ((i) + ((((u32)(i)) >> 5) << 2))

__global__ __launch_bounds__(256) void scan_kernel(
    const float* __restrict__ S0,
    float* __restrict__ Sout, int writeS)
{
    const float* Q    = scratch_resolve(ID_Q);
    const float* K    = scratch_resolve(ID_K);
    const float* V    = scratch_resolve(ID_V);
    const float* EG   = scratch_resolve(ID_EG);
    const float* BETA = scratch_resolve(ID_BETA);
    float*       O    = scratch_resolve(ID_O);

    const int vh = blockIdx.x, h = blockIdx.y, b = blockIdx.z;
    const int tid = threadIdx.x;
    const int vloc = tid >> 2, kq = tid & 3;
    const int v = vh * 64 + vloc;
    const int ks = kq * 32;

    __shared__ float sbuf[4][4][SROW];   // [stage][k,q,v,eg][128 skewed]
    __shared__ float sbeta[4];

    const size_t rowbase = (size_t)b * Tc * HIDc + (size_t)h * DKc;

    ull S[16];
    {
        const float* s0p = S0 + (((size_t)(b * Hc + h) * DKc + ks) * DVc + v);
#pragma unroll
        for (int j2 = 0; j2 < 16; j2++)
            S[j2] = f2pack(s0p[(size_t)(2 * j2) * DVc], s0p[(size_t)(2 * j2 + 1) * DVc]);
    }

    const int grp = tid >> 6, idx = tid & 63;
    const float* srcs[4] = {K, Q, V, EG};

#pragma unroll
    for (int t = 0; t < 2; t++) {
        if (idx < 32)
            cp16(&sbuf[t][grp][idx * 4 + ((idx >> 3) << 2)],
                 srcs[grp] + rowbase + (size_t)t * HIDc + idx * 4);
        if (tid == 0) cp4(&sbeta[t], BETA + ((size_t)(b * Tc + t)) * Hc + h);
        cp_commit();
    }

    for (int t = 0; t < Tc; t++) {
        if (t + 2 < Tc) {
            const int st = (t + 2) & 3;
            if (idx < 32)
                cp16(&sbuf[st][grp][idx * 4 + ((idx >> 3) << 2)],
                     srcs[grp] + rowbase + (size_t)(t + 2) * HIDc + idx * 4);
            if (tid == 0) cp4(&sbeta[st], BETA + ((size_t)(b * Tc + t + 2)) * Hc + h);
            cp_commit();
            asm volatile("cp.async.wait_group 2;" ::: "memory");
        } else {
            asm volatile("cp.async.wait_group 0;" ::: "memory");
        }
        __syncthreads();

        const int cb = t & 3;
        const float beta = sbeta[cb];
        const float vv = sbuf[cb][2][SKW(v)];
        const int kb = ks + kq * 4;

        ull k2[16];
        ull kva = 0ull, kvb = 0ull;
#pragma unroll
        for (int j2 = 0; j2 < 16; j2 += 2) {
            k2[j2]     = *(const ull*)&sbuf[cb][0][kb + 2 * j2];
            k2[j2 + 1] = *(const ull*)&sbuf[cb][0][kb + 2 * j2 + 2];
            ull e0 = *(const ull*)&sbuf[cb][3][kb + 2 * j2];
            ull e1 = *(const ull*)&sbuf[cb][3][kb + 2 * j2 + 2];
            S[j2]     = fmul2(S[j2],     e0);
            S[j2 + 1] = fmul2(S[j2 + 1], e1);
            kva = ffma2(k2[j2],     S[j2],     kva);
            kvb = ffma2(k2[j2 + 1], S[j2 + 1], kvb);
        }
        ull kv2 = fadd2(kva, kvb);
        float2 kvp = f2unpack(kv2);
        float kv = kvp.x + kvp.y;
        kv += __shfl_xor_sync(0xffffffffu, kv, 1);
        kv += __shfl_xor_sync(0xffffffffu, kv, 2);

        const float delta = (vv - kv) * beta;
        const ull d2 = f2pack(delta, delta);

        ull oa = 0ull, ob = 0ull;
#pragma unroll
        for (int j2 = 0; j2 < 16; j2 += 2) {
            S[j2]     = ffma2(k2[j2],     d2, S[j2]);
            S[j2 + 1] = ffma2(k2[j2 + 1], d2, S[j2 + 1]);
            ull q0 = *(const ull*)&sbuf[cb][1][kb + 2 * j2];
            ull q1 = *(const ull*)&sbuf[cb][1][kb + 2 * j2 + 2];
            oa = ffma2(q0, S[j2],     oa);
            ob = ffma2(q1, S[j2 + 1], ob);
        }
        ull o2 = fadd2(oa, ob);
        float2 op = f2unpack(o2);
        float o = op.x + op.y;
        o += __shfl_xor_sync(0xffffffffu, o, 1);
        o += __shfl_xor_sync(0xffffffffu, o, 2);
        if (kq == 0)
            O[rowbase + (size_t)t * HIDc + v] = o;
    }

    if (writeS) {
        float* sp = Sout + (((size_t)(b * Hc + h) * DKc + ks) * DVc + v);
#pragma unroll
        for (int j2 = 0; j2 < 16; j2++) {
            float2 c = f2unpack(S[j2]);
            sp[(size_t)(2 * j2) * DVc]     = c.x;
            sp[(size_t)(2 * j2 + 1) * DVc] = c.y;
        }
    }
}

// ------------------------------ host launcher ------------------------------
extern "C" void kernel_launch(void* const* d_in, const int* in_sizes, int n_in,
                              void* d_out, int out_size)
{
    const float* h      = (const float*)d_in[0];
    const float* S0     = (const float*)d_in[1];
    const float* q_w    = (const float*)d_in[2];
    const float* k_w    = (const float*)d_in[3];
    const float* v_w    = (const float*)d_in[4];
    const float* f_w0   = (const float*)d_in[5];
    const float* f_w1   = (const float*)d_in[6];
    const float* b_w    = (const float*)d_in[7];
    const float* A_log  = (const float*)d_in[8];
    const float* dt_b   = (const float*)d_in[9];
    const float* g_w0   = (const float*)d_in[10];
    const float* g_w1   = (const float*)d_in[11];
    const float* g_b1   = (const float*)d_in[12];
    const float* o_nw   = (const float*)d_in[13];
    const float* o_w    = (const float*)d_in[14];
    float* out = (float*)d_out;

    constexpr int GSMEM128 = GemmSmem<128>::TOTAL;   // 72 KB
    constexpr int GSMEM64  = GemmSmem<64>::TOTAL;    // 48 KB

    cudaFuncSetAttribute((const void*)mma_gemm<0,128>, cudaFuncAttributeMaxDynamicSharedMemorySize, GSMEM128);
    cudaFuncSetAttribute((const void*)mma_gemm<2,128>, cudaFuncAttributeMaxDynamicSharedMemorySize, GSMEM128);
    cudaFuncSetAttribute((const void*)mma_gemm<3,128>, cudaFuncAttributeMaxDynamicSharedMemorySize, GSMEM128);
    cudaFuncSetAttribute((const void*)mma_gemm<5,128>, cudaFuncAttributeMaxDynamicSharedMemorySize, GSMEM128);
    cudaFuncSetAttribute((const void*)mma_gemm<0,64>,  cudaFuncAttributeMaxDynamicSharedMemorySize, GSMEM64);

    const dim3 g_big(HIDc / 128, Mc / 128);       // (16, 64)
    const dim3 g_qkv(HIDc / 128, Mc / 128, 3);    // (16, 64, 3)
    const dim3 g_skny(1, Mc / 64, 2);             // (1, 128, 2)

    // 1. merged split (h: hi+lo; weights: hi)
    split_all<<<CUM8, 256>>>(h, q_w, k_w, v_w, o_w, f_w0, g_w0, f_w1, g_w1);

    // 2. beta
    beta_kernel<<<Mc, 512>>>(h, b_w);

    // 3. merged skinny GEMMs (z=0: f path -> TMP; z=1: g path -> TMP2), MT=64
    mma_gemm<0,64><<<g_skny, 256, GSMEM64>>>(OFF_HB_HI, OFF_HB_LO, OFF_FW0_HI,
                                             nullptr, -2, 128, HIDc, nullptr, nullptr,
                                             OFF_TMP_HI, OFF_TMP_LO,
                                             BS_W0, (size_t)2 * Mc * 128);

    // 4. eg = exp(-exp(A_log)*softplus(tmp@f_w1^T + dt_bias))
    mma_gemm<2,128><<<g_big, 256, GSMEM128>>>(OFF_TMP_HI, OFF_TMP_LO, OFF_FW1_HI,
                                              nullptr, ID_EG, HIDc, 128, A_log, dt_b,
                                              0, 0, 0, 0);

    // 5. sigf = sigmoid(tmp2@g_w1^T + g_b1)
    mma_gemm<3,128><<<g_big, 256, GSMEM128>>>(OFF_TMP2_HI, OFF_TMP2_LO, OFF_GW1_HI,
                                              nullptr, ID_SIGF, HIDc, 128, g_b1, nullptr,
                                              0, 0, 0, 0);

    // 6. merged q/k/v projections (z selects weight + epilogue) — ncu target
    mma_gemm<5,128><<<g_qkv, 256, GSMEM128>>>(OFF_HB_HI, OFF_HB_LO, OFF_WQ_HI,
                                              nullptr, ID_Q, HIDc, HIDc, nullptr, nullptr,
                                              0, 0, BS_W, 0);

    // 7. recurrent scan
    const size_t out_elems = (size_t)Mc * HIDc;                 // 16,777,216
    const size_t s_elems   = (size_t)Bc * Hc * DKc * DVc;       //  1,048,576
    const int writeS = ((size_t)out_size >= out_elems + s_elems) ? 1 : 0;
    scan_kernel<<<dim3(2, Hc, Bc), 256>>>(S0, out + out_elems, writeS);

    // 8-9. gated rms norm (emits fp16 hi/lo) + final projection
    gate_kernel<<<dim3(Hc, Mc), 128>>>(o_nw);
    mma_gemm<0,128><<<g_big, 256, GSMEM128>>>(OFF_OG_HI, OFF_OG_LO, OFF_WO_HI,
                                              out, -1, HIDc, HIDc, nullptr, nullptr,
                                              0, 0, 0, 0);
}

// round 17
// speedup vs baseline: 1.5678x; 1.5678x over previous
#include <cuda_runtime.h>
#include <cuda_fp16.h>
#include <cuda_bf16.h>
#include <cstdint>

// ---------------------------------------------------------------------------
// KimiDeltaAttention — mma.sync fp16 GEMMs (A hi/lo split, W fp16; 2 MMAs per
// product, fp32 accum; 3-stage pipeline, fused l2norm epilogue, merged qkv,
// z-merged skinny GEMMs at fixed 128x128 tile) + fp32 scan.
// B=4, T=2048, HID=2048, H=16, DK=DV=128
// compute_103 PTX only (no 'a' features): tensor path = mma.sync m16n8k16 f16.
// R17: reverted to R14's measured-good fixed-128 GEMM; only change is
// generalized z-strides so both skinny GEMMs share one grid(1,64,2) launch.
// ---------------------------------------------------------------------------

#define Bc 4
#define Tc 2048
#define HIDc 2048
#define Hc 16
#define DKc 128
#define DVc 128
#define Mc (Bc * Tc)            // 8192 rows

typedef unsigned long long ull;
typedef unsigned int u32;

// ------------------------- fp32 scratch (device globals) -------------------
__device__ float g_q   [(size_t)Mc * HIDc];
__device__ float g_k   [(size_t)Mc * HIDc];
__device__ float g_v   [(size_t)Mc * HIDc];
__device__ float g_eg  [(size_t)Mc * HIDc];   // exp(gate)
__device__ float g_sigf[(size_t)Mc * HIDc];   // sigmoid(factor)
__device__ float g_o   [(size_t)Mc * HIDc];
__device__ float g_beta[(size_t)Mc * Hc];

#define ID_Q    0
#define ID_K    1
#define ID_V    2
#define ID_EG   3
#define ID_SIGF 4
#define ID_O    5
#define ID_BETA 6

__device__ __forceinline__ float* scratch_resolve(int id) {
    switch (id) {
        case ID_Q:    return g_q;
        case ID_K:    return g_k;
        case ID_V:    return g_v;
        case ID_EG:   return g_eg;
        case ID_SIGF: return g_sigf;
        case ID_O:    return g_o;
        default:      return g_beta;
    }
}

// ------------------------- fp16 split pool ---------------------------------
constexpr size_t BS_W       = (size_t)HIDc * HIDc;
constexpr size_t BS_W0      = (size_t)128 * HIDc;
constexpr size_t OFF_HB_HI  = 0;
constexpr size_t OFF_HB_LO  = OFF_HB_HI  + (size_t)Mc * HIDc;
constexpr size_t OFF_WQ_HI  = OFF_HB_LO  + (size_t)Mc * HIDc;   // WQ,WK,WV consecutive
constexpr size_t OFF_WK_HI  = OFF_WQ_HI  + BS_W;
constexpr size_t OFF_WV_HI  = OFF_WK_HI  + BS_W;
constexpr size_t OFF_WO_HI  = OFF_WV_HI  + BS_W;
constexpr size_t OFF_FW0_HI = OFF_WO_HI  + BS_W;                // FW0,GW0 consecutive
constexpr size_t OFF_GW0_HI = OFF_FW0_HI + BS_W0;
constexpr size_t OFF_FW1_HI = OFF_GW0_HI + BS_W0;
constexpr size_t OFF_GW1_HI = OFF_FW1_HI + (size_t)HIDc * 128;
constexpr size_t OFF_TMP_HI = OFF_GW1_HI + (size_t)HIDc * 128;  // TMP,TMP2 blocks consecutive
constexpr size_t OFF_TMP_LO = OFF_TMP_HI + (size_t)Mc * 128;
constexpr size_t OFF_TMP2_HI= OFF_TMP_LO + (size_t)Mc * 128;
constexpr size_t OFF_TMP2_LO= OFF_TMP2_HI+ (size_t)Mc * 128;
constexpr size_t OFF_OG_HI  = OFF_TMP2_LO+ (size_t)Mc * 128;
constexpr size_t OFF_OG_LO  = OFF_OG_HI  + (size_t)Mc * HIDc;
constexpr size_t HF_TOTAL   = OFF_OG_LO  + (size_t)Mc * HIDc;

__device__ __half g_hfpool[HF_TOTAL];

// ------------------------------ f32x2 helpers ------------------------------
__device__ __forceinline__ ull f2pack(float a, float b) {
    ull r; asm("mov.b64 %0, {%1, %2};" : "=l"(r) : "f"(a), "f"(b)); return r;
}
__device__ __forceinline__ float2 f2unpack(ull x) {
    float2 r; asm("mov.b64 {%0, %1}, %2;" : "=f"(r.x), "=f"(r.y) : "l"(x)); return r;
}
__device__ __forceinline__ ull ffma2(ull a, ull b, ull c) {
    ull d; asm("fma.rn.f32x2 %0, %1, %2, %3;" : "=l"(d) : "l"(a), "l"(b), "l"(c)); return d;
}
__device__ __forceinline__ ull fmul2(ull a, ull b) {
    ull d; asm("mul.rn.f32x2 %0, %1, %2;" : "=l"(d) : "l"(a), "l"(b)); return d;
}
__device__ __forceinline__ ull fadd2(ull a, ull b) {
    ull d; asm("add.rn.f32x2 %0, %1, %2;" : "=l"(d) : "l"(a), "l"(b)); return d;
}

// ------------------------------ async copy ---------------------------------
__device__ __forceinline__ void cp16(void* s, const void* g) {
    u32 sa = (u32)__cvta_generic_to_shared(s);
    asm volatile("cp.async.ca.shared.global [%0], [%1], 16;" :: "r"(sa), "l"(g));
}
__device__ __forceinline__ void cp16u(u32 s, const void* g) {
    asm volatile("cp.async.cg.shared.global [%0], [%1], 16;" :: "r"(s), "l"(g));
}
__device__ __forceinline__ void cp4(void* s, const void* g) {
    u32 sa = (u32)__cvta_generic_to_shared(s);
    asm volatile("cp.async.ca.shared.global [%0], [%1], 4;" :: "r"(sa), "l"(g));
}
__device__ __forceinline__ void cp_commit() { asm volatile("cp.async.commit_group;"); }

__device__ __forceinline__ u32 smem_u32(const void* p) {
    return (u32)__cvta_generic_to_shared(p);
}

// ------------------------------ mma helpers --------------------------------
__device__ __forceinline__ void mma16816(float* c, const u32* a, const u32* b) {
    asm volatile(
        "mma.sync.aligned.m16n8k16.row.col.f32.f16.f16.f32 "
        "{%0,%1,%2,%3}, {%4,%5,%6,%7}, {%8,%9}, {%0,%1,%2,%3};"
        : "+f"(c[0]), "+f"(c[1]), "+f"(c[2]), "+f"(c[3])
        : "r"(a[0]), "r"(a[1]), "r"(a[2]), "r"(a[3]), "r"(b[0]), "r"(b[1]));
}
__device__ __forceinline__ void ldsm4(u32* r, u32 addr) {
    asm volatile("ldmatrix.sync.aligned.m8n8.x4.shared.b16 {%0,%1,%2,%3}, [%4];"
        : "=r"(r[0]), "=r"(r[1]), "=r"(r[2]), "=r"(r[3]) : "r"(addr));
}

// ------------------------------ merged split -------------------------------
constexpr u32 NB_HB  = (u32)((size_t)Mc * HIDc / 1024);    // 16384
constexpr u32 NB_W   = (u32)(BS_W / 1024);                  //  4096
constexpr u32 NB_W0  = (u32)(BS_W0 / 1024);                 //   256
constexpr u32 CUM0 = NB_HB;                  // h
constexpr u32 CUM1 = CUM0 + NB_W;            // q_w
constexpr u32 CUM2 = CUM1 + NB_W;            // k_w
constexpr u32 CUM3 = CUM2 + NB_W;            // v_w
constexpr u32 CUM4 = CUM3 + NB_W;            // o_w
constexpr u32 CUM5 = CUM4 + NB_W0;           // f_w0
constexpr u32 CUM6 = CUM5 + NB_W0;           // g_w0
constexpr u32 CUM7 = CUM6 + NB_W0;           // f_w1
constexpr u32 CUM8 = CUM7 + NB_W0;           // g_w1  (total 33792)

__global__ __launch_bounds__(256) void split_all(
    const float* __restrict__ h,   const float* __restrict__ q_w,
    const float* __restrict__ k_w, const float* __restrict__ v_w,
    const float* __restrict__ o_w, const float* __restrict__ f_w0,
    const float* __restrict__ g_w0,const float* __restrict__ f_w1,
    const float* __restrict__ g_w1)
{
    const u32 b = blockIdx.x;
    const float* src; size_t off_hi; size_t off_lo = 0; u32 b0;
    if      (b < CUM0) { src = h;    off_hi = OFF_HB_HI;  off_lo = OFF_HB_LO; b0 = 0; }
    else if (b < CUM1) { src = q_w;  off_hi = OFF_WQ_HI;  b0 = CUM0; }
    else if (b < CUM2) { src = k_w;  off_hi = OFF_WK_HI;  b0 = CUM1; }
    else if (b < CUM3) { src = v_w;  off_hi = OFF_WV_HI;  b0 = CUM2; }
    else if (b < CUM4) { src = o_w;  off_hi = OFF_WO_HI;  b0 = CUM3; }
    else if (b < CUM5) { src = f_w0; off_hi = OFF_FW0_HI; b0 = CUM4; }
    else if (b < CUM6) { src = g_w0; off_hi = OFF_GW0_HI; b0 = CUM5; }
    else if (b < CUM7) { src = f_w1; off_hi = OFF_FW1_HI; b0 = CUM6; }
    else               { src = g_w1; off_hi = OFF_GW1_HI; b0 = CUM7; }

    size_t i = ((size_t)(b - b0) * 256 + threadIdx.x) * 4;
    float4 x = *(const float4*)(src + i);
    __half h0 = __float2half_rn(x.x), h1 = __float2half_rn(x.y);
    __half h2 = __float2half_rn(x.z), h3 = __float2half_rn(x.w);
    uint2 ph;
    ph.x = (u32)__half_as_ushort(h0) | ((u32)__half_as_ushort(h1) << 16);
    ph.y = (u32)__half_as_ushort(h2) | ((u32)__half_as_ushort(h3) << 16);
    *(uint2*)(g_hfpool + off_hi + i) = ph;
    if (off_lo) {
        __half l0 = __float2half_rn(x.x - __half2float(h0));
        __half l1 = __float2half_rn(x.y - __half2float(h1));
        __half l2 = __float2half_rn(x.z - __half2float(h2));
        __half l3 = __float2half_rn(x.w - __half2float(h3));
        uint2 pl;
        pl.x = (u32)__half_as_ushort(l0) | ((u32)__half_as_ushort(l1) << 16);
        pl.y = (u32)__half_as_ushort(l2) | ((u32)__half_as_ushort(l3) << 16);
        *(uint2*)(g_hfpool + off_lo + i) = pl;
    }
}

// ------------------------- mma.sync fp16 GEMM ------------------------------
// C[M,N] = act( A[M,K] @ W[N,K]^T ), A split hi/lo, W fp16-hi:
//   D += Ahi*Whi + Alo*Whi   (fp32 accumulators)
// CTA tile 128x128, 256 thr (8 warps 2x4; warp tile 64x32), BK=32, 3-stage
// cp.async pipeline (ONE barrier per chunk), XOR-swizzled smem, ldmatrix.
// ACT: 0 none | 2 kda-gate->exp | 3 sigmoid(x+aux1[n])
//      | 5 merged qkv: z=0 silu+l2norm*0.0884, z=1 silu+l2norm, z=2 silu
// Output: Cid>=0 scratch fp32 (ACT5: id Cid+z) | -1 Cext fp32 | -2 fp16 hi/lo.
// z strides: weight block = w_hi + z*w_zstride; fp16 out = (o_hi/o_lo)+z*o_zstride.
constexpr int BKg         = 32;
constexpr int TILE_BYTES  = 128 * BKg * 2;     // 8 KB
constexpr int STAGE_BYTES = 3 * TILE_BYTES;    // 24 KB (Ahi, Alo, Whi)
constexpr int GSMEM       = 3 * STAGE_BYTES;   // 72 KB

template <int ACT>
__global__ __launch_bounds__(256) void mma_gemm(
    size_t a_hi, size_t a_lo, size_t w_hi,
    float* __restrict__ Cext, int Cid, int Ntot, int Ktot,
    const float* __restrict__ aux1, const float* __restrict__ aux2,
    size_t o_hi, size_t o_lo, size_t w_zstride, size_t o_zstride)
{
    extern __shared__ char dsm[];
    const u32 sb = smem_u32(dsm);
    const int tid = threadIdx.x, lane = tid & 31, wid = tid >> 5;
    const int warp_m = wid & 1, warp_n = wid >> 1;    // 2 x 4 warp grid
    const int bm = blockIdx.y, bn = blockIdx.x, bz = blockIdx.z;

    const __half* srcs[3] = {
        g_hfpool + a_hi + (size_t)bm * 128 * Ktot,
        g_hfpool + a_lo + (size_t)bm * 128 * Ktot,
        g_hfpool + w_hi + (size_t)bz * w_zstride + (size_t)bn * 128 * Ktot };

    float acc[4][4][4];
#pragma unroll
    for (int i = 0; i < 4; i++)
#pragma unroll
        for (int j = 0; j < 4; j++)
#pragma unroll
            for (int e = 0; e < 4; e++) acc[i][j][e] = 0.f;

    const int NC = Ktot / BKg;
    const int jq = lane >> 3, rq = lane & 7;
    const int jlow = jq & 1, jhi = jq >> 1;

    auto load_stage = [&](int stage, int c) {
        u32 base = sb + (u32)stage * STAGE_BYTES;
#pragma unroll
        for (int t = 0; t < 3; t++) {
            const __half* src = srcs[t] + (size_t)c * BKg;
            u32 tb = base + (u32)t * TILE_BYTES;
#pragma unroll
            for (int i = 0; i < 2; i++) {
                int idx = tid + i * 256;                 // 0..511
                u32 row = (u32)(idx >> 2), g = (u32)(idx & 3);
                u32 so = tb + row * 64u + ((g ^ (row & 3u)) * 16u);
                cp16u(so, (const char*)(src + (size_t)row * Ktot) + g * 16);
            }
        }
    };

    load_stage(0, 0); cp_commit();
    load_stage(1, 1); cp_commit();

    int s_cur = 0, s_pre = 2;     // compute stage; prefetch stage (c+2)%3
    for (int c = 0; c < NC; c++) {
        if (c == NC - 1) {
            asm volatile("cp.async.wait_group 0;" ::: "memory");
        } else {
            asm volatile("cp.async.wait_group 1;" ::: "memory");
        }
        __syncthreads();
        // prefetch AFTER barrier: stage s_pre == (c-1)%3, readers provably done.
        if (c + 2 < NC) {
            load_stage(s_pre, c + 2); cp_commit();
        }

        const u32 base = sb + (u32)s_cur * STAGE_BYTES;
        const u32 ah = base, al = base + TILE_BYTES;
        const u32 wh = base + 2 * TILE_BYTES;

#pragma unroll
        for (int ks = 0; ks < 2; ks++) {
            const u32 g = (u32)(ks * 2 + jhi);
            u32 a_hi_f[4][4], a_lo_f[4][4];
#pragma unroll
            for (int mi = 0; mi < 4; mi++) {
                u32 row = (u32)(warp_m * 64 + mi * 16 + jlow * 8 + rq);
                u32 off = row * 64u + ((g ^ (row & 3u)) * 16u);
                ldsm4(a_hi_f[mi], ah + off);
                ldsm4(a_lo_f[mi], al + off);
            }
            u32 b_hi_f[4][2];
#pragma unroll
            for (int pi = 0; pi < 2; pi++) {
                u32 row = (u32)(warp_n * 32 + pi * 16 + jlow * 8 + rq);
                u32 off = row * 64u + ((g ^ (row & 3u)) * 16u);
                u32 t0[4];
                ldsm4(t0, wh + off);
                b_hi_f[2*pi][0] = t0[0]; b_hi_f[2*pi][1] = t0[2];
                b_hi_f[2*pi+1][0] = t0[1]; b_hi_f[2*pi+1][1] = t0[3];
            }
#pragma unroll
            for (int mi = 0; mi < 4; mi++)
#pragma unroll
                for (int ni = 0; ni < 4; ni++) {
                    mma16816(acc[mi][ni], a_hi_f[mi], b_hi_f[ni]);
                    mma16816(acc[mi][ni], a_lo_f[mi], b_hi_f[ni]);
                }
        }
        s_cur = (s_cur == 2) ? 0 : s_cur + 1;
        s_pre = (s_pre == 2) ? 0 : s_pre + 1;
    }

    // ---------------- epilogue ----------------
    const int qrow = lane >> 2, qcol = (lane & 3) * 2;
    const int n_warp0 = bn * 128 + warp_n * 32;

    if (ACT == 5) {
        // silu always; z<2 additionally l2norm per head-row.
#pragma unroll
        for (int mi = 0; mi < 4; mi++)
#pragma unroll
            for (int ni = 0; ni < 4; ni++)
#pragma unroll
                for (int e = 0; e < 4; e++) {
                    float x = acc[mi][ni][e];
                    acc[mi][ni][e] = x / (1.0f + expf(-x));
                }
        float* C = scratch_resolve(Cid + bz);
        if (bz < 2) {
            const float sscale = (bz == 0) ? 0.08838834764831845f : 1.0f;
            __syncthreads();                      // stage buffers reusable
            float* red = (float*)dsm;             // [128 rows][4 warp_n]
#pragma unroll
            for (int mi = 0; mi < 4; mi++)
#pragma unroll
                for (int half = 0; half < 2; half++) {
                    float ss = 0.f;
#pragma unroll
                    for (int ni = 0; ni < 4; ni++) {
                        float x0 = acc[mi][ni][half * 2];
                        float x1 = acc[mi][ni][half * 2 + 1];
                        ss += x0 * x0 + x1 * x1;
                    }
                    ss += __shfl_xor_sync(0xffffffffu, ss, 1);
                    ss += __shfl_xor_sync(0xffffffffu, ss, 2);
                    if ((lane & 3) == 0) {
                        int rowl = warp_m * 64 + mi * 16 + half * 8 + qrow;
                        red[rowl * 4 + warp_n] = ss;
                    }
                }
            __syncthreads();
#pragma unroll
            for (int mi = 0; mi < 4; mi++)
#pragma unroll
                for (int half = 0; half < 2; half++) {
                    int rowl = warp_m * 64 + mi * 16 + half * 8 + qrow;
                    float tot = red[rowl * 4] + red[rowl * 4 + 1]
                              + red[rowl * 4 + 2] + red[rowl * 4 + 3];
                    float r = rsqrtf(tot + 1e-6f) * sscale;
                    const int m = bm * 128 + rowl;
                    float* crow = C + (size_t)m * Ntot + n_warp0;
#pragma unroll
                    for (int ni = 0; ni < 4; ni++) {
                        float2 o2;
                        o2.x = acc[mi][ni][half * 2]     * r;
                        o2.y = acc[mi][ni][half * 2 + 1] * r;
                        *(float2*)(crow + ni * 8 + qcol) = o2;
                    }
                }
        } else {
#pragma unroll
            for (int mi = 0; mi < 4; mi++)
#pragma unroll
                for (int half = 0; half < 2; half++) {
                    const int m = bm * 128 + warp_m * 64 + mi * 16 + half * 8 + qrow;
                    float* crow = C + (size_t)m * Ntot + n_warp0;
#pragma unroll
                    for (int ni = 0; ni < 4; ni++) {
                        float2 o2;
                        o2.x = acc[mi][ni][half * 2];
                        o2.y = acc[mi][ni][half * 2 + 1];
                        *(float2*)(crow + ni * 8 + qcol) = o2;
                    }
                }
        }
        return;
    }

    float* C = (Cid >= 0) ? scratch_resolve(Cid) : Cext;
    const size_t oh = o_hi + (size_t)bz * o_zstride;
    const size_t ol = o_lo + (size_t)bz * o_zstride;
#pragma unroll
    for (int mi = 0; mi < 4; mi++) {
#pragma unroll
        for (int half = 0; half < 2; half++) {
            const int m = bm * 128 + warp_m * 64 + mi * 16 + half * 8 + qrow;
#pragma unroll
            for (int ni = 0; ni < 4; ni++) {
                float x0 = acc[mi][ni][half * 2];
                float x1 = acc[mi][ni][half * 2 + 1];
                const int n = n_warp0 + ni * 8 + qcol;
                if (ACT == 2) {
                    float a0 = expf(aux1[n >> 7]);
                    float a1 = expf(aux1[(n + 1) >> 7]);
                    float s0 = x0 + aux2[n], s1 = x1 + aux2[n + 1];
                    s0 = (s0 > 20.0f) ? s0 : log1pf(expf(s0));
                    s1 = (s1 > 20.0f) ? s1 : log1pf(expf(s1));
                    x0 = expf(-a0 * s0); x1 = expf(-a1 * s1);
                } else if (ACT == 3) {
                    x0 = 1.0f / (1.0f + expf(-(x0 + aux1[n])));
                    x1 = 1.0f / (1.0f + expf(-(x1 + aux1[n + 1])));
                }
                if (Cid == -2) {
                    __half h0 = __float2half_rn(x0), h1 = __float2half_rn(x1);
                    __half l0 = __float2half_rn(x0 - __half2float(h0));
                    __half l1 = __float2half_rn(x1 - __half2float(h1));
                    size_t base = (size_t)m * Ntot + n;
                    *(u32*)(g_hfpool + oh + base) =
                        (u32)__half_as_ushort(h0) | ((u32)__half_as_ushort(h1) << 16);
                    *(u32*)(g_hfpool + ol + base) =
                        (u32)__half_as_ushort(l0) | ((u32)__half_as_ushort(l1) << 16);
                } else {
                    float2 o2; o2.x = x0; o2.y = x1;
                    *(float2*)(C + (size_t)m * Ntot + n) = o2;
                }
            }
        }
    }
}

// --------------------------- beta = sigmoid(h @ b_w^T) ---------------------
__global__ __launch_bounds__(512) void beta_kernel(
    const float* __restrict__ H, const float* __restrict__ BW)
{
    float* BETA = scratch_resolve(ID_BETA);
    const int m = blockIdx.x;
    const int w = threadIdx.x >> 5, lane = threadIdx.x & 31;
    const float4* hr = (const float4*)(H + (size_t)m * HIDc);
    const float4* br = (const float4*)(BW + (size_t)w * HIDc);
    float s = 0.f;
#pragma unroll 4
    for (int i = lane; i < HIDc / 4; i += 32) {
        float4 a = hr[i], b = br[i];
        s += a.x * b.x + a.y * b.y + a.z * b.z + a.w * b.w;
    }
#pragma unroll
    for (int off = 16; off > 0; off >>= 1)
        s += __shfl_xor_sync(0xffffffffu, s, off);
    if (lane == 0) BETA[(size_t)m * Hc + w] = 1.0f / (1.0f + expf(-s));
}

// ---------- gated RMS norm: og = rms(o)*w*sigf, emitted as fp16 hi/lo ------
__global__ __launch_bounds__(128) void gate_kernel(const float* __restrict__ NW)
{
    const float* O    = scratch_resolve(ID_O);
    const float* SIGF = scratch_resolve(ID_SIGF);
    const int h = blockIdx.x, m = blockIdx.y;
    const int v = threadIdx.x;
    const size_t off = (size_t)m * HIDc + (size_t)h * DVc + v;
    float x = O[off];
    float s = x * x;
#pragma unroll
    for (int o = 16; o > 0; o >>= 1) s += __shfl_xor_sync(0xffffffffu, s, o);
    __shared__ float red[4];
    if ((v & 31) == 0) red[v >> 5] = s;
    __syncthreads();
    float tot = red[0] + red[1] + red[2] + red[3];
    float r = rsqrtf(tot * (1.0f / DVc) + 1e-5f);
    float y = x * r * NW[v] * SIGF[off];
    __half hi = __float2half_rn(y);
    __half lo = __float2half_rn(y - __half2float(hi));
    g_hfpool[OFF_OG_HI + off] = hi;
    g_hfpool[OFF_OG_LO + off] = lo;
}

// ------------------------------ recurrent scan -----------------------------
// grid (2, H, B); 256 threads. CTA owns 64 v-cols; 4 threads split the 128-k
// dim (kq = tid&3, 32 k each, 16 state pairs/thread). 4 smem stages, prefetch
// distance 2 -> single barrier per step. Rows skewed +4 floats per 32-block.
#define SROW 144
#define SKW(i) ((i) + ((((u32)(i)) >> 5) << 2))

__global__ __launch_bounds__(256) void scan_kernel(
    const float* __restrict__ S0,
    float* __restrict__ Sout, int writeS)
{
    const float* Q    = scratch_resolve(ID_Q);
    const float* K    = scratch_resolve(ID_K);
    const float* V    = scratch_resolve(ID_V);
    const float* EG   = scratch_resolve(ID_EG);
    const float* BETA = scratch_resolve(ID_BETA);
    float*       O    = scratch_resolve(ID_O);

    const int vh = blockIdx.x, h = blockIdx.y, b = blockIdx.z;
    const int tid = threadIdx.x;
    const int vloc = tid >> 2, kq = tid & 3;
    const int v = vh * 64 + vloc;
    const int ks = kq * 32;

    __shared__ float sbuf[4][4][SROW];   // [stage][k,q,v,eg][128 skewed]
    __shared__ float sbeta[4];

    const size_t rowbase = (size_t)b * Tc * HIDc + (size_t)h * DKc;

    ull S[16];
    {
        const float* s0p = S0 + (((size_t)(b * Hc + h) * DKc + ks) * DVc + v);
#pragma unroll
        for (int j2 = 0; j2 < 16; j2++)
            S[j2] = f2pack(s0p[(size_t)(2 * j2) * DVc], s0p[(size_t)(2 * j2 + 1) * DVc]);
    }

    const int grp = tid >> 6, idx = tid & 63;
    const float* srcs[4] = {K, Q, V, EG};

#pragma unroll
    for (int t = 0; t < 2; t++) {
        if (idx < 32)
            cp16(&sbuf[t][grp][idx * 4 + ((idx >> 3) << 2)],
                 srcs[grp] + rowbase + (size_t)t * HIDc + idx * 4);
        if (tid == 0) cp4(&sbeta[t], BETA + ((size_t)(b * Tc + t)) * Hc + h);
        cp_commit();
    }

    for (int t = 0; t < Tc; t++) {
        if (t + 2 < Tc) {
            const int st = (t + 2) & 3;
            if (idx < 32)
                cp16(&sbuf[st][grp][idx * 4 + ((idx >> 3) << 2)],
                     srcs[grp] + rowbase + (size_t)(t + 2) * HIDc + idx * 4);
            if (tid == 0) cp4(&sbeta[st], BETA + ((size_t)(b * Tc + t + 2)) * Hc + h);
            cp_commit();
            asm volatile("cp.async.wait_group 2;" ::: "memory");
        } else {
            asm volatile("cp.async.wait_group 0;" ::: "memory");
        }
        __syncthreads();

        const int cb = t & 3;
        const float beta = sbeta[cb];
        const float vv = sbuf[cb][2][SKW(v)];
        const int kb = ks + kq * 4;        // skewed base for this k-quarter

        ull k2[16];
        ull kva = 0ull, kvb = 0ull;
#pragma unroll
        for (int j2 = 0; j2 < 16; j2 += 2) {
            k2[j2]     = *(const ull*)&sbuf[cb][0][kb + 2 * j2];
            k2[j2 + 1] = *(const ull*)&sbuf[cb][0][kb + 2 * j2 + 2];
            ull e0 = *(const ull*)&sbuf[cb][3][kb + 2 * j2];
            ull e1 = *(const ull*)&sbuf[cb][3][kb + 2 * j2 + 2];
            S[j2]     = fmul2(S[j2],     e0);
            S[j2 + 1] = fmul2(S[j2 + 1], e1);
            kva = ffma2(k2[j2],     S[j2],     kva);
            kvb = ffma2(k2[j2 + 1], S[j2 + 1], kvb);
        }
        ull kv2 = fadd2(kva, kvb);
        float2 kvp = f2unpack(kv2);
        float kv = kvp.x + kvp.y;
        kv += __shfl_xor_sync(0xffffffffu, kv, 1);
        kv += __shfl_xor_sync(0xffffffffu, kv, 2);

        const float delta = (vv - kv) * beta;
        const ull d2 = f2pack(delta, delta);

        ull oa = 0ull, ob = 0ull;
#pragma unroll
        for (int j2 = 0; j2 < 16; j2 += 2) {
            S[j2]     = ffma2(k2[j2],     d2, S[j2]);
            S[j2 + 1] = ffma2(k2[j2 + 1], d2, S[j2 + 1]);
            ull q0 = *(const ull*)&sbuf[cb][1][kb + 2 * j2];
            ull q1 = *(const ull*)&sbuf[cb][1][kb + 2 * j2 + 2];
            oa = ffma2(q0, S[j2],     oa);
            ob = ffma2(q1, S[j2 + 1], ob);
        }
        ull o2 = fadd2(oa, ob);
        float2 op = f2unpack(o2);
        float o = op.x + op.y;
        o += __shfl_xor_sync(0xffffffffu, o, 1);
        o += __shfl_xor_sync(0xffffffffu, o, 2);
        if (kq == 0)
            O[rowbase + (size_t)t * HIDc + v] = o;
    }

    if (writeS) {
        float* sp = Sout + (((size_t)(b * Hc + h) * DKc + ks) * DVc + v);
#pragma unroll
        for (int j2 = 0; j2 < 16; j2++) {
            float2 c = f2unpack(S[j2]);
            sp[(size_t)(2 * j2) * DVc]     = c.x;
            sp[(size_t)(2 * j2 + 1) * DVc] = c.y;
        }
    }
}

// ------------------------------ host launcher ------------------------------
extern "C" void kernel_launch(void* const* d_in, const int* in_sizes, int n_in,
                              void* d_out, int out_size)
{
    const float* h      = (const float*)d_in[0];
    const float* S0     = (const float*)d_in[1];
    const float* q_w    = (const float*)d_in[2];
    const float* k_w    = (const float*)d_in[3];
    const float* v_w    = (const float*)d_in[4];
    const float* f_w0   = (const float*)d_in[5];
    const float* f_w1   = (const float*)d_in[6];
    const float* b_w    = (const float*)d_in[7];
    const float* A_log  = (const float*)d_in[8];
    const float* dt_b   = (const float*)d_in[9];
    const float* g_w0   = (const float*)d_in[10];
    const float* g_w1   = (const float*)d_in[11];
    const float* g_b1   = (const float*)d_in[12];
    const float* o_nw   = (const float*)d_in[13];
    const float* o_w    = (const float*)d_in[14];
    float* out = (float*)d_out;

    cudaFuncSetAttribute(mma_gemm<0>, cudaFuncAttributeMaxDynamicSharedMemorySize, GSMEM);
    cudaFuncSetAttribute(mma_gemm<2>, cudaFuncAttributeMaxDynamicSharedMemorySize, GSMEM);
    cudaFuncSetAttribute(mma_gemm<3>, cudaFuncAttributeMaxDynamicSharedMemorySize, GSMEM);
    cudaFuncSetAttribute(mma_gemm<5>, cudaFuncAttributeMaxDynamicSharedMemorySize, GSMEM);

    const dim3 g_big(HIDc / 128, Mc / 128);       // (16, 64)
    const dim3 g_qkv(HIDc / 128, Mc / 128, 3);    // (16, 64, 3)
    const dim3 g_skny(1, Mc / 128, 2);            // (1, 64, 2) -> 128 CTAs

    // 1. merged split (h: hi+lo; weights: hi)
    split_all<<<CUM8, 256>>>(h, q_w, k_w, v_w, o_w, f_w0, g_w0, f_w1, g_w1);

    // 2. beta
    beta_kernel<<<Mc, 512>>>(h, b_w);

    // 3. z-merged skinny GEMMs (z=0: f path -> TMP; z=1: g path -> TMP2)
    mma_gemm<0><<<g_skny, 256, GSMEM>>>(OFF_HB_HI, OFF_HB_LO, OFF_FW0_HI,
                                        nullptr, -2, 128, HIDc, nullptr, nullptr,
                                        OFF_TMP_HI, OFF_TMP_LO,
                                        BS_W0, (size_t)2 * Mc * 128);

    // 4. eg = exp(-exp(A_log)*softplus(tmp@f_w1^T + dt_bias))
    mma_gemm<2><<<g_big, 256, GSMEM>>>(OFF_TMP_HI, OFF_TMP_LO, OFF_FW1_HI,
                                       nullptr, ID_EG, HIDc, 128, A_log, dt_b,
                                       0, 0, 0, 0);

    // 5. sigf = sigmoid(tmp2@g_w1^T + g_b1)
    mma_gemm<3><<<g_big, 256, GSMEM>>>(OFF_TMP2_HI, OFF_TMP2_LO, OFF_GW1_HI,
                                       nullptr, ID_SIGF, HIDc, 128, g_b1, nullptr,
                                       0, 0, 0, 0);

    // 6. merged q/k/v projections (z selects weight + epilogue)
    mma_gemm<5><<<g_qkv, 256, GSMEM>>>(OFF_HB_HI, OFF_HB_LO, OFF_WQ_HI,
                                       nullptr, ID_Q, HIDc, HIDc, nullptr, nullptr,
                                       0, 0, BS_W, 0);

    // 7. recurrent scan
    const size_t out_elems = (size_t)Mc * HIDc;                 // 16,777,216
    const size_t s_elems   = (size_t)Bc * Hc * DKc * DVc;       //  1,048,576
    const int writeS = ((size_t)out_size >= out_elems + s_elems) ? 1 : 0;
    scan_kernel<<<dim3(2, Hc, Bc), 256>>>(S0, out + out_elems, writeS);

    // 8-9. gated rms norm (emits fp16 hi/lo) + final projection
    gate_kernel<<<dim3(Hc, Mc), 128>>>(o_nw);
    mma_gemm<0><<<g_big, 256, GSMEM>>>(OFF_OG_HI, OFF_OG_LO, OFF_WO_HI,
                                       out, -1, HIDc, HIDc, nullptr, nullptr,
                                       0, 0, 0, 0);
}